// round 1
// baseline (speedup 1.0000x reference)
#include <cuda_runtime.h>
#include <math.h>
#include <float.h>

#define BB 4
#define TH 120
#define STEPS 8
#define DIN 32
#define DM 512
#define NH 8
#define NL 4
#define DFF 2048
#define NSUB 5
#define DH 64
#define TT 128
#define MR (BB*TT)          /* 512 rows total */
#define SCALE 22.62741699796952f
#define LN_EPS 1e-5f

// ------------------------- device state -------------------------
__device__ float g_buf[BB*TT*DIN];
__device__ float g_pe[TT*DM];
__device__ float g_h[MR*DM];
__device__ float g_qkv[MR*3*DM];
__device__ float g_attn[MR*DM];
__device__ float g_ff[MR*DFF];
__device__ float g_part[4*MR*DM];
__device__ float g_wqkv[NL*3*DM*DM];
__device__ float g_wembT[DIN*DM];
__device__ float g_weff[DFF*DIN];
__device__ float g_wbemb[DFF];
__device__ float g_vbase[BB*DFF];

__device__ __forceinline__ const float* asel_ptr(int s){
    switch(s){ case 0: return g_h; case 1: return g_attn; default: return g_ff; }
}
__device__ __forceinline__ float* csel_ptr(int s, int z){
    switch(s){ case 0: return g_qkv; case 1: return g_ff; default: return g_part + (size_t)z*(MR*DM); }
}

__device__ __forceinline__ float gelu_f(float x){
    float u = 0.7978845608028654f*(x + 0.044715f*x*x*x);
    float e = expf(2.0f*u);
    float t = 1.0f - 2.0f/(e + 1.0f);   // tanh(u), robust under fast-math
    return 0.5f*x*(1.0f + t);
}

// ------------------------- precompute kernels -------------------------
__global__ void init_kernel(const float* __restrict__ history){
    int idx = blockIdx.x*blockDim.x + threadIdx.x;
    if (idx >= BB*TT*DIN) return;
    int c = idx % DIN; int t = (idx/DIN) % TT; int b = idx/(DIN*TT);
    g_buf[idx] = (t < TH) ? history[(b*TH + t)*DIN + c] : 0.0f;
}

__global__ void pe_kernel(){
    int idx = blockIdx.x*blockDim.x + threadIdx.x;
    if (idx >= TT*DM) return;
    int t = idx / DM, c = idx % DM;
    int i2 = c & ~1;
    double div = exp((double)i2 * (-9.210340371976184/(double)DM));
    double a = (double)t * div;
    g_pe[idx] = (float)((c & 1) ? cos(a) : sin(a));
}

__global__ void wembT_kernel(const float* __restrict__ W_emb){
    int idx = blockIdx.x*blockDim.x + threadIdx.x;
    if (idx >= DIN*DM) return;
    int k = idx / DM, n = idx % DM;
    g_wembT[idx] = W_emb[n*DIN + k];
}

// Weff = Wr1[:, :512] @ W_emb  (2048 x 32);  wbemb = Wr1[:, :512] @ b_emb
__global__ void weff_kernel(const float* __restrict__ Wr1,
                            const float* __restrict__ W_emb,
                            const float* __restrict__ b_emb){
    int i = blockIdx.x;       // 0..2047
    int j = threadIdx.x;      // 0..31
    float s = 0.f;
    for (int k = 0; k < DM; k++)
        s = fmaf(Wr1[i*(2*DM) + k], W_emb[k*DIN + j], s);
    g_weff[i*DIN + j] = s;
    float t = 0.f;
    for (int k = j; k < DM; k += 32)
        t = fmaf(Wr1[i*(2*DM) + k], b_emb[k], t);
    #pragma unroll
    for (int o = 16; o; o >>= 1) t += __shfl_xor_sync(0xffffffffu, t, o);
    if (j == 0) g_wbemb[i] = t;
}

__global__ void pack_wqkv_kernel(const float* __restrict__ Wq,
                                 const float* __restrict__ Wk,
                                 const float* __restrict__ Wv){
    int idx = blockIdx.x*blockDim.x + threadIdx.x;
    if (idx >= NL*3*DM*DM) return;
    int c = idx % DM; int r = (idx/DM) % (3*DM); int l = idx/(3*DM*DM);
    float v;
    if (r < DM)        v = Wq[(l*DM + r)*DM + c];
    else if (r < 2*DM) v = Wk[(l*DM + (r-DM))*DM + c];
    else               v = Wv[(l*DM + (r-2*DM))*DM + c];
    g_wqkv[idx] = v;
}

// ------------------------- per-step kernels -------------------------
__global__ void embed_kernel(const float* __restrict__ b_emb){
    __shared__ float row[DIN];
    int m = blockIdx.x;            // 0..511 (= b*TT + t)
    int t = m & (TT-1);
    int n = threadIdx.x;           // 0..511
    if (n < DIN) row[n] = g_buf[m*DIN + n];
    __syncthreads();
    float s = 0.f;
    #pragma unroll
    for (int k = 0; k < DIN; k++)
        s = fmaf(row[k], g_wembT[k*DM + n], s);
    g_h[m*DM + n] = (s + b_emb[n])*SCALE + g_pe[t*DM + n];
}

// generic fp32 NT gemm over M=512 rows; optional K-split via blockIdx.z
template<int BM,int BN,int BK,int TM,int TN>
__global__ void gemm_kernel(int asel, const float* __restrict__ Wext, int qkv_layer,
                            const float* __restrict__ bias, int do_gelu,
                            int csel, int Kfull, int Ksub, int ldc){
    constexpr int NTH = (BM/TM)*(BN/TN);
    __shared__ float As[BK][BM+4];
    __shared__ float Ws[BK][BN+4];
    const float* A = asel_ptr(asel);
    const float* W = (qkv_layer >= 0) ? (g_wqkv + (size_t)qkv_layer*3*DM*DM) : Wext;
    float* C = csel_ptr(csel, blockIdx.z);
    int m0 = blockIdx.y*BM, n0 = blockIdx.x*BN;
    int kbase = blockIdx.z * Ksub;
    int tid = threadIdx.x;
    int tn = tid % (BN/TN), tm = tid / (BN/TN);
    float acc[TM][TN] = {};
    for (int k0 = 0; k0 < Ksub; k0 += BK){
        for (int i = tid; i < BM*BK/4; i += NTH){
            int row = i/(BK/4), q = (i%(BK/4))*4;
            float4 v = *reinterpret_cast<const float4*>(A + (size_t)(m0+row)*Kfull + kbase + k0 + q);
            As[q+0][row]=v.x; As[q+1][row]=v.y; As[q+2][row]=v.z; As[q+3][row]=v.w;
        }
        for (int i = tid; i < BN*BK/4; i += NTH){
            int row = i/(BK/4), q = (i%(BK/4))*4;
            float4 v = *reinterpret_cast<const float4*>(W + (size_t)(n0+row)*Kfull + kbase + k0 + q);
            Ws[q+0][row]=v.x; Ws[q+1][row]=v.y; Ws[q+2][row]=v.z; Ws[q+3][row]=v.w;
        }
        __syncthreads();
        #pragma unroll
        for (int k = 0; k < BK; k++){
            float a[TM], b[TN];
            #pragma unroll
            for (int i = 0; i < TM; i++) a[i] = As[k][tm*TM+i];
            #pragma unroll
            for (int j = 0; j < TN; j++) b[j] = Ws[k][tn*TN+j];
            #pragma unroll
            for (int i = 0; i < TM; i++)
                #pragma unroll
                for (int j = 0; j < TN; j++)
                    acc[i][j] = fmaf(a[i], b[j], acc[i][j]);
        }
        __syncthreads();
    }
    #pragma unroll
    for (int i = 0; i < TM; i++){
        int m = m0 + tm*TM + i;
        #pragma unroll
        for (int j = 0; j < TN; j++){
            int n = n0 + tn*TN + j;
            float c = acc[i][j];
            if (bias) c += bias[n];
            if (do_gelu) c = gelu_f(c);
            C[(size_t)m*ldc + n] = c;
        }
    }
}

// attention: one block per (head, batch); 512 threads (16 warps), warp-per-q-row
__global__ void attn_kernel(){
    extern __shared__ float sm[];
    float* qs = sm;                        // [128][64]
    float* ks = sm + TT*DH;                // [128][65]
    float* vs = ks + TT*(DH+1);            // [128][65]
    float* wb = vs + TT*(DH+1);            // [16][128]
    int hd = blockIdx.x, b = blockIdx.y;
    int tid = threadIdx.x;
    int wid = tid >> 5, lane = tid & 31;
    for (int i = tid; i < TT*(DH/4); i += 512){
        int t = i/(DH/4), q4 = (i%(DH/4))*4;
        const float* base = g_qkv + (size_t)(b*TT + t)*(3*DM) + hd*DH + q4;
        float4 vq = *reinterpret_cast<const float4*>(base);
        float4 vk = *reinterpret_cast<const float4*>(base + DM);
        float4 vv = *reinterpret_cast<const float4*>(base + 2*DM);
        qs[t*DH+q4+0]=vq.x; qs[t*DH+q4+1]=vq.y; qs[t*DH+q4+2]=vq.z; qs[t*DH+q4+3]=vq.w;
        ks[t*(DH+1)+q4+0]=vk.x; ks[t*(DH+1)+q4+1]=vk.y; ks[t*(DH+1)+q4+2]=vk.z; ks[t*(DH+1)+q4+3]=vk.w;
        vs[t*(DH+1)+q4+0]=vv.x; vs[t*(DH+1)+q4+1]=vv.y; vs[t*(DH+1)+q4+2]=vv.z; vs[t*(DH+1)+q4+3]=vv.w;
    }
    __syncthreads();
    for (int q = wid; q < TT; q += 16){
        float l[4];
        #pragma unroll
        for (int j = 0; j < 4; j++){
            int kr = lane + 32*j;
            float s = 0.f;
            #pragma unroll
            for (int d = 0; d < DH; d++)
                s = fmaf(qs[q*DH+d], ks[kr*(DH+1)+d], s);
            // mask: attend only where k > q (anti-causal, faithful to source).
            // row 127 has no valid k: all lanes get -FLT_MAX -> exp(0)=1 -> uniform 1/128, matching jax.
            l[j] = (kr > q) ? (s * 0.125f) : -FLT_MAX;
        }
        float mx = fmaxf(fmaxf(l[0],l[1]), fmaxf(l[2],l[3]));
        #pragma unroll
        for (int o = 16; o; o >>= 1) mx = fmaxf(mx, __shfl_xor_sync(0xffffffffu, mx, o));
        float p[4], sum = 0.f;
        #pragma unroll
        for (int j = 0; j < 4; j++){ p[j] = expf(l[j]-mx); sum += p[j]; }
        #pragma unroll
        for (int o = 16; o; o >>= 1) sum += __shfl_xor_sync(0xffffffffu, sum, o);
        float inv = 1.0f/sum;
        #pragma unroll
        for (int j = 0; j < 4; j++) wb[wid*TT + lane + 32*j] = p[j]*inv;
        __syncwarp();
        float o0 = 0.f, o1 = 0.f;
        for (int kr = 0; kr < TT; kr++){
            float w = wb[wid*TT + kr];
            o0 = fmaf(w, vs[kr*(DH+1)+lane],    o0);
            o1 = fmaf(w, vs[kr*(DH+1)+lane+32], o1);
        }
        float* op = g_attn + (size_t)(b*TT+q)*DM + hd*DH;
        op[lane] = o0; op[lane+32] = o1;
    }
}

__device__ __forceinline__ float block_sum256(float v, float* red){
    #pragma unroll
    for (int o = 16; o; o >>= 1) v += __shfl_xor_sync(0xffffffffu, v, o);
    int wid = threadIdx.x >> 5, lane = threadIdx.x & 31;
    if (lane == 0) red[wid] = v;
    __syncthreads();
    if (wid == 0){
        float t = (lane < 8) ? red[lane] : 0.f;
        #pragma unroll
        for (int o = 4; o; o >>= 1) t += __shfl_xor_sync(0xffffffffu, t, o);
        if (lane == 0) red[0] = t;
    }
    __syncthreads();
    float r = red[0];
    __syncthreads();
    return r;
}

// x = h + sum_z part[z] + bias; h <- LN(x)*g + b
__global__ void ln_sum_kernel(int nsplits, const float* __restrict__ bias,
                              const float* __restrict__ gam, const float* __restrict__ bet){
    __shared__ float red[8];
    int m = blockIdx.x, tid = threadIdx.x;      // 256 threads
    float x0 = g_h[(size_t)m*DM + tid];
    float x1 = g_h[(size_t)m*DM + tid + 256];
    for (int z = 0; z < nsplits; z++){
        x0 += g_part[(size_t)z*MR*DM + m*DM + tid];
        x1 += g_part[(size_t)z*MR*DM + m*DM + tid + 256];
    }
    if (bias){ x0 += bias[tid]; x1 += bias[tid+256]; }
    float mu  = block_sum256(x0 + x1, red) * (1.0f/DM);
    float d0 = x0 - mu, d1 = x1 - mu;
    float var = block_sum256(d0*d0 + d1*d1, red) * (1.0f/DM);
    float rstd = 1.0f/sqrtf(var + LN_EPS);
    g_h[(size_t)m*DM + tid]       = d0*rstd*gam[tid]     + bet[tid];
    g_h[(size_t)m*DM + tid + 256] = d1*rstd*gam[tid+256] + bet[tid+256];
}

// vbase[b] = Wr1[:,512:] @ ctx + br1 + SCALE*wbemb;  ctx = h[b, ctx_row]
__global__ void vbase_kernel(const float* __restrict__ Wr1, const float* __restrict__ br1,
                             int ctx_row){
    __shared__ float ctx[DM];
    int b = blockIdx.y;
    int tid = threadIdx.x;     // 128
    for (int i = tid; i < DM; i += 128) ctx[i] = g_h[(size_t)(b*TT + ctx_row)*DM + i];
    __syncthreads();
    int wid = tid >> 5, lane = tid & 31;
    for (int rr = 0; rr < 32; rr++){
        int r = blockIdx.x*128 + wid*32 + rr;
        float s = 0.f;
        for (int k = lane; k < DM; k += 32)
            s = fmaf(Wr1[(size_t)r*(2*DM) + DM + k], ctx[k], s);
        #pragma unroll
        for (int o = 16; o; o >>= 1) s += __shfl_xor_sync(0xffffffffu, s, o);
        if (lane == 0) g_vbase[b*DFF + r] = s + br1[r] + SCALE*g_wbemb[r];
    }
}

// 5 refine substeps entirely in one block per batch (uses Weff folding)
__global__ void refine_kernel(const float* __restrict__ Wr2, const float* __restrict__ br2,
                              float* __restrict__ out, int s){
    __shared__ float cur[DIN];
    __shared__ float hidden[DFF];
    int b = blockIdx.x, tid = threadIdx.x;   // 1024 threads
    int ptr = TH + s;
    if (tid < DIN) cur[tid] = g_buf[(size_t)(b*TT + ptr-1)*DIN + tid];
    __syncthreads();
    int wid = tid >> 5, lane = tid & 31;     // 32 warps == DIN outputs
    for (int it = 0; it < NSUB; it++){
        for (int r = tid; r < DFF; r += 1024){
            float sd = 0.f;
            #pragma unroll
            for (int j = 0; j < DIN; j++)
                sd = fmaf(g_weff[r*DIN + j], cur[j], sd);
            hidden[r] = gelu_f(SCALE*sd + g_vbase[b*DFF + r]);
        }
        __syncthreads();
        float dsum = 0.f;
        for (int k = lane; k < DFF; k += 32)
            dsum = fmaf(Wr2[(size_t)wid*DFF + k], hidden[k], dsum);
        #pragma unroll
        for (int o = 16; o; o >>= 1) dsum += __shfl_xor_sync(0xffffffffu, dsum, o);
        if (lane == 0) cur[wid] += dsum + br2[wid];
        __syncthreads();
    }
    if (tid < DIN){
        float v = cur[tid];
        g_buf[(size_t)(b*TT + ptr)*DIN + tid] = v;
        out[(size_t)(b*STEPS + s)*DIN + tid] = v;
    }
}

// ------------------------- host driver -------------------------
#define ATTN_SMEM ((TT*DH + 2*TT*(DH+1) + 16*TT)*(int)sizeof(float))

extern "C" void kernel_launch(void* const* d_in, const int* in_sizes, int n_in,
                              void* d_out, int out_size){
    const float* history = (const float*)d_in[0];
    /* d_in[1] = steps (always 8, hardcoded) */
    const float* W_emb = (const float*)d_in[2];
    const float* b_emb = (const float*)d_in[3];
    const float* Wq    = (const float*)d_in[4];
    const float* Wk    = (const float*)d_in[5];
    const float* Wv    = (const float*)d_in[6];
    const float* Wo    = (const float*)d_in[7];
    const float* ln1_g = (const float*)d_in[8];
    const float* ln1_b = (const float*)d_in[9];
    const float* W1    = (const float*)d_in[10];
    const float* b1    = (const float*)d_in[11];
    const float* W2    = (const float*)d_in[12];
    const float* b2    = (const float*)d_in[13];
    const float* ln2_g = (const float*)d_in[14];
    const float* ln2_b = (const float*)d_in[15];
    const float* Wr1   = (const float*)d_in[16];
    const float* br1   = (const float*)d_in[17];
    const float* Wr2   = (const float*)d_in[18];
    const float* br2   = (const float*)d_in[19];
    float* out = (float*)d_out;

    cudaFuncSetAttribute(attn_kernel, cudaFuncAttributeMaxDynamicSharedMemorySize, ATTN_SMEM);

    init_kernel<<<(BB*TT*DIN+255)/256, 256>>>(history);
    pe_kernel<<<(TT*DM+255)/256, 256>>>();
    wembT_kernel<<<(DIN*DM+255)/256, 256>>>(W_emb);
    weff_kernel<<<DFF, 32>>>(Wr1, W_emb, b_emb);
    pack_wqkv_kernel<<<(NL*3*DM*DM+255)/256, 256>>>(Wq, Wk, Wv);

    for (int s = 0; s < STEPS; s++){
        embed_kernel<<<MR, DM>>>(b_emb);
        for (int l = 0; l < NL; l++){
            // QKV: [512 x 1536] = h @ packed(Wq,Wk,Wv)^T
            gemm_kernel<64,64,16,4,4><<<dim3(3*DM/64, MR/64, 1), 256>>>(
                0, nullptr, l, nullptr, 0, /*C=qkv*/0, DM, DM, 3*DM);
            attn_kernel<<<dim3(NH, BB), 512, ATTN_SMEM>>>();
            // proj: attn @ Wo^T, split-K=2 into g_part
            gemm_kernel<64,64,16,4,4><<<dim3(DM/64, MR/64, 2), 256>>>(
                1, Wo + (size_t)l*DM*DM, -1, nullptr, 0, /*C=part*/2, DM, DM/2, DM);
            ln_sum_kernel<<<MR, 256>>>(2, nullptr, ln1_g + l*DM, ln1_b + l*DM);
            // FF1: gelu(h @ W1^T + b1)
            gemm_kernel<64,64,16,4,4><<<dim3(DFF/64, MR/64, 1), 256>>>(
                0, W1 + (size_t)l*DFF*DM, -1, b1 + l*DFF, 1, /*C=ff*/1, DM, DM, DFF);
            // FF2: ff @ W2^T, split-K=4 into g_part
            gemm_kernel<64,64,16,4,4><<<dim3(DM/64, MR/64, 4), 256>>>(
                2, W2 + (size_t)l*DM*DFF, -1, nullptr, 0, /*C=part*/2, DFF, DFF/4, DM);
            ln_sum_kernel<<<MR, 256>>>(4, b2 + l*DM, ln2_g + l*DM, ln2_b + l*DM);
        }
        vbase_kernel<<<dim3(16, BB), 128>>>(Wr1, br1, TH + s - 1);
        refine_kernel<<<BB, 1024>>>(Wr2, br2, out, s);
    }
}